// round 16
// baseline (speedup 1.0000x reference)
#include <cuda_runtime.h>
#include <cuda_bf16.h>
#include <cstdint>

#define B_   2
#define S_   2048
#define DM_  1024
#define H_   16
#define HD_  64
#define KD_  1024

// tcgen05 is only legal in arch-specific (sm_103a) compilation passes.
#if defined(__CUDA_ARCH__) && \
    (defined(__CUDA_ARCH_FEAT_SM103_ALL) || \
     (defined(__CUDA_ARCH_SPECIFIC__)) || \
     (defined(__CUDA_ARCH_FAMILY_SPECIFIC__)))
#define HAS_TCGEN05 1
#else
#define HAS_TCGEN05 0
#endif

// Scratch (allocation-free).
// g_Xt / g_W*t / g_Yt: tf32-bit u32 pre-packed GEMM operands.
// Q/K pre-split into bf16 hi/lo [B,H,S,HD] (Q carries rope * 1/sqrt(HD) * log2e).
// V pre-converted tf32 bits TRANSPOSED [B,H,HD,S].
__device__ uint32_t g_Xt  [B_*S_*DM_];
__device__ uint32_t g_Wqt [DM_*DM_];
__device__ uint32_t g_Wkt [DM_*DM_];
__device__ uint32_t g_Wvt [DM_*DM_];
__device__ uint32_t g_Wot [DM_*DM_];
__device__ uint32_t g_Yt  [B_*S_*DM_];
__device__ uint16_t g_Qhib[B_*H_*S_*HD_];
__device__ uint16_t g_Qlob[B_*H_*S_*HD_];
__device__ uint16_t g_Khib[B_*H_*S_*HD_];
__device__ uint16_t g_Klob[B_*H_*S_*HD_];
__device__ uint32_t g_Vt  [B_*H_*HD_*S_];

enum { MODE_PLAIN = 0, MODE_Q = 1, MODE_K = 2, MODE_V = 3 };

#define QSCALE 0.1803368801111204f   // 0.125 * log2(e)

// ---------------------------------------------------------------------------
// PTX helpers
// ---------------------------------------------------------------------------
__device__ __forceinline__ uint32_t smem_to_u32(const void* p) {
    uint32_t a;
    asm("{ .reg .u64 t; cvta.to.shared.u64 t, %1; cvt.u32.u64 %0, t; }" : "=r"(a) : "l"(p));
    return a;
}
__device__ __forceinline__ uint32_t elect_one_pred() {
    uint32_t pred;
    asm volatile("{\n\t.reg .pred p;\n\telect.sync _|p, 0xFFFFFFFF;\n\tselp.b32 %0, 1, 0, p;\n\t}" : "=r"(pred));
    return pred;
}
#define MBARRIER_INIT(addr, cnt) \
    asm volatile("mbarrier.init.shared.b64 [%0], %1;" :: "r"((uint32_t)(addr)), "r"((uint32_t)(cnt)) : "memory")
#define MBARRIER_INVAL(addr) \
    asm volatile("mbarrier.inval.shared.b64 [%0];" :: "r"((uint32_t)(addr)) : "memory")
#define MBARRIER_WAIT_PARITY(mbar_smem_addr, phase_parity) do { \
    uint32_t _mbar = (uint32_t)(mbar_smem_addr); \
    uint32_t _parity = (uint32_t)(phase_parity); \
    uint32_t _done; \
    asm volatile("{\n\t.reg .pred p;\n\t" \
        "mbarrier.try_wait.parity.acquire.cta.shared::cta.b64 p, [%1], %2;\n\t" \
        "selp.b32 %0, 1, 0, p;\n\t}" : "=r"(_done) : "r"(_mbar), "r"(_parity) : "memory"); \
    if (!_done) { \
        asm volatile("{\n\t.reg .pred P1;\n\t" \
            "WAIT_LOOP_%=:\n\t" \
            "mbarrier.try_wait.parity.acquire.cta.shared::cta.b64 P1, [%0], %1, 0x989680;\n\t" \
            "@P1 bra.uni WAIT_DONE_%=;\n\t" \
            "bra.uni WAIT_LOOP_%=;\n\t" \
            "WAIT_DONE_%=:\n\t}" :: "r"(_mbar), "r"(_parity) : "memory"); \
    } \
} while(0)

#define TCGEN05_ALLOC(smem_result_addr, nCols) \
    asm volatile("tcgen05.alloc.cta_group::1.sync.aligned.shared::cta.b32 [%0], %1;" \
        :: "r"((uint32_t)(smem_result_addr)), "r"((uint32_t)(nCols)) : "memory")
#define TCGEN05_DEALLOC(tmem_addr, nCols) \
    asm volatile("tcgen05.dealloc.cta_group::1.sync.aligned.b32 %0, %1;" :: "r"(tmem_addr), "r"((uint32_t)(nCols)))
#define TCGEN05_RELINQUISH() \
    asm volatile("tcgen05.relinquish_alloc_permit.cta_group::1.sync.aligned;")
#define TCGEN05_COMMIT(mbar_smem_addr) \
    asm volatile("tcgen05.commit.cta_group::1.mbarrier::arrive::one.shared::cluster.b64 [%0];" \
        :: "r"((uint32_t)(mbar_smem_addr)) : "memory")
#define TCGEN05_FENCE_AFTER()  asm volatile("tcgen05.fence::after_thread_sync;" ::: "memory")
#define TCGEN05_FENCE_BEFORE() asm volatile("tcgen05.fence::before_thread_sync;" ::: "memory")
#define TCGEN05_WAIT_LD()      asm volatile("tcgen05.wait::ld.sync.aligned;" ::: "memory")
#define TCGEN05_WAIT_ST()      asm volatile("tcgen05.wait::st.sync.aligned;" ::: "memory")
#define FENCE_PROXY_ASYNC_SHARED_CTA() asm volatile("fence.proxy.async.shared::cta;" ::: "memory")

#define CP_ASYNC16(dst, src) \
    asm volatile("cp.async.cg.shared.global [%0], [%1], 16;" :: "r"((uint32_t)(dst)), "l"(src) : "memory")
#define CP_COMMIT() asm volatile("cp.async.commit_group;" ::: "memory")
#define CP_WAIT0()  asm volatile("cp.async.wait_group 0;" ::: "memory")
#define CP_WAIT1()  asm volatile("cp.async.wait_group 1;" ::: "memory")

#define NAMED_BAR_ARRIVE(id, cnt) \
    asm volatile("bar.arrive %0, %1;" :: "r"(id), "r"(cnt) : "memory")
#define NAMED_BAR_SYNC(id, cnt) \
    asm volatile("bar.sync %0, %1;" :: "r"(id), "r"(cnt) : "memory")

#define TCGEN05_LD_32X32B_X32(r, tmem_addr) \
    asm volatile("tcgen05.ld.sync.aligned.32x32b.x32.b32 " \
        "{%0, %1, %2, %3, %4, %5, %6, %7, " \
        " %8, %9, %10, %11, %12, %13, %14, %15, " \
        " %16, %17, %18, %19, %20, %21, %22, %23, " \
        " %24, %25, %26, %27, %28, %29, %30, %31}, [%32];" \
        : "=r"((r)[0]),  "=r"((r)[1]),  "=r"((r)[2]),  "=r"((r)[3]), \
          "=r"((r)[4]),  "=r"((r)[5]),  "=r"((r)[6]),  "=r"((r)[7]), \
          "=r"((r)[8]),  "=r"((r)[9]),  "=r"((r)[10]), "=r"((r)[11]), \
          "=r"((r)[12]), "=r"((r)[13]), "=r"((r)[14]), "=r"((r)[15]), \
          "=r"((r)[16]), "=r"((r)[17]), "=r"((r)[18]), "=r"((r)[19]), \
          "=r"((r)[20]), "=r"((r)[21]), "=r"((r)[22]), "=r"((r)[23]), \
          "=r"((r)[24]), "=r"((r)[25]), "=r"((r)[26]), "=r"((r)[27]), \
          "=r"((r)[28]), "=r"((r)[29]), "=r"((r)[30]), "=r"((r)[31]) \
        : "r"(tmem_addr))

#define TCGEN05_ST_32X32B_X32(tmem_addr, r) \
    asm volatile("tcgen05.st.sync.aligned.32x32b.x32.b32 [%0], " \
        "{%1, %2, %3, %4, %5, %6, %7, %8, " \
        " %9, %10, %11, %12, %13, %14, %15, %16, " \
        " %17, %18, %19, %20, %21, %22, %23, %24, " \
        " %25, %26, %27, %28, %29, %30, %31, %32};" \
        :: "r"(tmem_addr), \
           "r"((r)[0]),  "r"((r)[1]),  "r"((r)[2]),  "r"((r)[3]), \
           "r"((r)[4]),  "r"((r)[5]),  "r"((r)[6]),  "r"((r)[7]), \
           "r"((r)[8]),  "r"((r)[9]),  "r"((r)[10]), "r"((r)[11]), \
           "r"((r)[12]), "r"((r)[13]), "r"((r)[14]), "r"((r)[15]), \
           "r"((r)[16]), "r"((r)[17]), "r"((r)[18]), "r"((r)[19]), \
           "r"((r)[20]), "r"((r)[21]), "r"((r)[22]), "r"((r)[23]), \
           "r"((r)[24]), "r"((r)[25]), "r"((r)[26]), "r"((r)[27]), \
           "r"((r)[28]), "r"((r)[29]), "r"((r)[30]), "r"((r)[31]) \
        : "memory")

// SMEM descriptor: SW128, version=1 (Blackwell), LBO=1, SBO=64 (K-major 128B rows)
static constexpr uint64_t SMEM_DESC_BASE_SW128 =
    (uint64_t(2)  << 61) | (uint64_t(1) << 46) | (uint64_t(64) << 32) | (uint64_t(1) << 16);
#define MAKE_SMEM_DESC(base_addr) (SMEM_DESC_BASE_SW128 | ((uint64_t)((base_addr) >> 4) & 0x3FFF))
#define SMEM_SWIZZLE_128B(off) ((off) ^ (((off) >> 3) & 0x70))

#if HAS_TCGEN05
// tf32 SS MMA, K=8 per dispatch.
__device__ __forceinline__ void mma_tf32_ss(uint32_t d_tmem, uint64_t a_desc, uint64_t b_desc,
                                            uint32_t idesc, uint32_t enable_d) {
    asm volatile(
        "{\n\t.reg .pred p;\n\t"
        "setp.ne.u32 p, %4, 0;\n\t"
        "tcgen05.mma.cta_group::1.kind::tf32 [%0], %1, %2, %3, {%5, %5, %5, %5}, p;\n\t}"
        :: "r"(d_tmem), "l"(a_desc), "l"(b_desc), "r"(idesc), "r"(enable_d), "r"(0u)
        : "memory");
}
// bf16 SS MMA (kind::f16), K=16 per dispatch.
__device__ __forceinline__ void mma_bf16_ss(uint32_t d_tmem, uint64_t a_desc, uint64_t b_desc,
                                            uint32_t idesc, uint32_t enable_d) {
    asm volatile(
        "{\n\t.reg .pred p;\n\t"
        "setp.ne.u32 p, %4, 0;\n\t"
        "tcgen05.mma.cta_group::1.kind::f16 [%0], %1, %2, %3, {%5, %5, %5, %5}, p;\n\t}"
        :: "r"(d_tmem), "l"(a_desc), "l"(b_desc), "r"(idesc), "r"(enable_d), "r"(0u)
        : "memory");
}
// tf32 TS MMA (A in TMEM), K=8 per dispatch, A step = 8 cols.
__device__ __forceinline__ void mma_tf32_ts(uint32_t d_tmem, uint32_t a_tmem, uint64_t b_desc,
                                            uint32_t idesc, uint32_t enable_d) {
    asm volatile(
        "{\n\t.reg .pred p;\n\t"
        "setp.ne.u32 p, %4, 0;\n\t"
        "tcgen05.mma.cta_group::1.kind::tf32 [%0], [%1], %2, %3, {%5, %5, %5, %5}, p;\n\t}"
        :: "r"(d_tmem), "r"(a_tmem), "l"(b_desc), "r"(idesc), "r"(enable_d), "r"(0u)
        : "memory");
}
#endif

__device__ __forceinline__ uint32_t f2tf32(float x) {
    uint32_t r;
    asm("cvt.rna.tf32.f32 %0, %1;" : "=r"(r) : "f"(x));
    return r;
}

static constexpr uint32_t IDESC_TF32_N256 =
    (1u << 4) | (2u << 7) | (2u << 10) | ((256u / 8u) << 17) | ((128u / 16u) << 24);
static constexpr uint32_t IDESC_TF32_N64 =
    (1u << 4) | (2u << 7) | (2u << 10) | ((64u / 8u) << 17) | ((128u / 16u) << 24);
static constexpr uint32_t IDESC_BF16_N64 =
    (1u << 4) | (1u << 7) | (1u << 10) | ((64u / 8u) << 17) | ((128u / 16u) << 24);

__device__ __forceinline__ uint16_t bf16bits(float x) {
    __nv_bfloat16 h = __float2bfloat16_rn(x);
    return *reinterpret_cast<uint16_t*>(&h);
}
__device__ __forceinline__ float bf16val(uint16_t b) {
    __nv_bfloat16 h = *reinterpret_cast<__nv_bfloat16*>(&b);
    return __bfloat162float(h);
}

// ---------------------------------------------------------------------------
// Pack: f32 -> tf32-bit u32 (rna). Bit-identical to former per-CTA staging cvt.
// ---------------------------------------------------------------------------
__global__ __launch_bounds__(256)
void pack_tf32(const float* __restrict__ src, uint32_t* __restrict__ dst)
{
    const int i = (blockIdx.x * 256 + threadIdx.x) * 4;
    float4 v = *(const float4*)(src + i);
    *(uint4*)(dst + i) = make_uint4(f2tf32(v.x), f2tf32(v.y), f2tf32(v.z), f2tf32(v.w));
}

// ---------------------------------------------------------------------------
// GEMM: C[m,n] = sum_k A[m,k] * W[n,k].  M=4096, N=1024, K=1024.
// CTA tile 256x256: TWO 128-row M-blocks share one staged B tile
// (B L2 traffic halves: 128MB -> 64MB). Double-buffered cp.async + prefetch.
// TMEM: D0 @0 (256 cols), D1 @256 (256 cols).
// ---------------------------------------------------------------------------
#define GT_BK        32
#define GT_N         256
#define GT_NCHUNK    (KD_ / GT_BK)          // 32
#define GT_ATILE     (128 * GT_BK * 4)      // 16384 per m-block
#define GT_BTILE     (GT_N * GT_BK * 4)     // 32768
#define GT_CHUNK     (2 * GT_ATILE + GT_BTILE)  // 65536
#define SM_TMEMP     0
#define SM_BAR0      16
#define SM_BAR1      24
#define SM_TILES     1024
#define GT_SMEM_SZ   (SM_TILES + 2 * GT_CHUNK)  // 132096 -> occ 1

template<int MODE>
__global__ __launch_bounds__(256)
void gemm_tc(const uint32_t* __restrict__ At, float* __restrict__ Cout,
             const uint32_t* __restrict__ Wt,
             const int* __restrict__ use_rope, const int* __restrict__ tokpos,
             const float* __restrict__ cosT, const float* __restrict__ sinT)
{
    extern __shared__ char smem[];
    const int tid = threadIdx.x;
    const uint32_t* Ain = (MODE == MODE_PLAIN) ? g_Yt : At;

#if HAS_TCGEN05
    const uint32_t sb = smem_to_u32(smem);
    const int wid = tid >> 5;
    const int lid = tid & 31;
    const int m0 = blockIdx.y * 256, n0 = blockIdx.x * GT_N;

    if (wid == 0) {
        TCGEN05_ALLOC(sb + SM_TMEMP, 512);
        TCGEN05_RELINQUISH();
    }
    if (tid == 0) {
        MBARRIER_INIT(sb + SM_BAR0, 1);
        MBARRIER_INIT(sb + SM_BAR1, 1);
    }
    __syncthreads();
    uint32_t tmem_base;
    asm volatile("ld.shared.b32 %0, [%1];" : "=r"(tmem_base) : "r"(sb + SM_TMEMP));

    const uint32_t* A0base = Ain + (size_t)m0 * KD_;
    const uint32_t* A1base = Ain + (size_t)(m0 + 128) * KD_;
    const uint32_t* Bbase  = Wt  + (size_t)n0 * KD_;

    // Stage one K-chunk: A0 1024 + A1 1024 + B 2048 float4-units, 16/thread.
    auto stage_chunk = [&](int kc) {
        const uint32_t base = SM_TILES + (kc & 1) * GT_CHUNK;
        #pragma unroll
        for (int it = 0; it < 16; it++) {
            const int idx = tid + it * 256;
            if (it < 4) {
                const int row = idx >> 3, c4 = idx & 7;
                const uint32_t so = SMEM_SWIZZLE_128B((uint32_t)(row * 128 + c4 * 16));
                CP_ASYNC16(sb + base + so, A0base + (size_t)row * KD_ + kc * GT_BK + c4 * 4);
            } else if (it < 8) {
                const int a1 = idx - 1024;
                const int row = a1 >> 3, c4 = a1 & 7;
                const uint32_t so = SMEM_SWIZZLE_128B((uint32_t)(row * 128 + c4 * 16));
                CP_ASYNC16(sb + base + GT_ATILE + so, A1base + (size_t)row * KD_ + kc * GT_BK + c4 * 4);
            } else {
                const int bi = idx - 2048;
                const int row = bi >> 3, c4 = bi & 7;
                const uint32_t so = SMEM_SWIZZLE_128B((uint32_t)(row * 128 + c4 * 16));
                CP_ASYNC16(sb + base + 2 * GT_ATILE + so, Bbase + (size_t)row * KD_ + kc * GT_BK + c4 * 4);
            }
        }
        CP_COMMIT();
    };

    stage_chunk(0);
    int ph0 = 0, ph1 = 0;

    for (int kc = 0; kc < GT_NCHUNK; kc++) {
        const int buf = kc & 1;
        const uint32_t base = SM_TILES + buf * GT_CHUNK;

        if (kc + 1 < GT_NCHUNK) {
            if (kc >= 1) {
                if (buf == 1) { MBARRIER_WAIT_PARITY(sb + SM_BAR0, ph0); ph0 ^= 1; }
                else          { MBARRIER_WAIT_PARITY(sb + SM_BAR1, ph1); ph1 ^= 1; }
            }
            stage_chunk(kc + 1);
            CP_WAIT1();   // chunk kc's group complete (kc+1 still in flight)
        } else {
            CP_WAIT0();
        }
        FENCE_PROXY_ASYNC_SHARED_CTA();
        __syncthreads();

        if (wid == 0) {
            if (elect_one_pred()) {
                const uint64_t a0d = MAKE_SMEM_DESC(sb + base);
                const uint64_t a1d = MAKE_SMEM_DESC(sb + base + GT_ATILE);
                const uint64_t bd  = MAKE_SMEM_DESC(sb + base + 2 * GT_ATILE);
                #pragma unroll
                for (int s = 0; s < 4; s++)
                    mma_tf32_ss(tmem_base,       a0d + s * 2, bd + s * 2, IDESC_TF32_N256,
                                (kc > 0 || s > 0) ? 1u : 0u);
                #pragma unroll
                for (int s = 0; s < 4; s++)
                    mma_tf32_ss(tmem_base + 256, a1d + s * 2, bd + s * 2, IDESC_TF32_N256,
                                (kc > 0 || s > 0) ? 1u : 0u);
                TCGEN05_COMMIT(sb + (buf == 0 ? SM_BAR0 : SM_BAR1));
            }
        }
    }

    MBARRIER_WAIT_PARITY(sb + SM_BAR0, ph0);
    MBARRIER_WAIT_PARITY(sb + SM_BAR1, ph1);
    TCGEN05_FENCE_AFTER();

    // Epilogue: loop 2 m-blocks; thread (wid,lid) owns row; g = col group.
    const int g = tid >> 7;

    #pragma unroll
    for (int mb = 0; mb < 2; mb++) {
        const int m = m0 + mb * 128 + (wid & 3) * 32 + lid;
        const int b = m / S_, s = m % S_;
        const uint32_t tmD = tmem_base + mb * 256;

        #pragma unroll
        for (int cc = 0; cc < 4; cc++) {
            const int col0 = g * 128 + cc * 32;
            uint32_t d[32];
            TCGEN05_LD_32X32B_X32(d, tmD + col0);
            TCGEN05_WAIT_LD();
            float v[32];
            #pragma unroll
            for (int j = 0; j < 32; j++) v[j] = __uint_as_float(d[j]);

            if (MODE == MODE_PLAIN) {
                float* dst = Cout + (size_t)m * DM_ + n0 + col0;
                #pragma unroll
                for (int j4 = 0; j4 < 8; j4++)
                    *(float4*)(dst + j4 * 4) = make_float4(v[j4*4], v[j4*4+1], v[j4*4+2], v[j4*4+3]);
            } else if (MODE == MODE_V) {
                const int h  = (n0 + col0) >> 6;
                const int d0 = col0 & 63;        // 0 or 32
                uint32_t* dst = g_Vt + ((size_t)(b * H_ + h) * HD_ + d0) * S_ + s;
                #pragma unroll
                for (int j = 0; j < 32; j++) dst[(size_t)j * S_] = f2tf32(v[j]);
            } else {
                const int h  = (n0 + col0) >> 6;
                const int d0 = col0 & 63;        // 0 or 32
                if (use_rope[0]) {
                    const int pos = tokpos[s];
                    const int f0 = d0 >> 1;
                    #pragma unroll
                    for (int f2 = 0; f2 < 16; f2++) {
                        const float c = cosT[pos * 32 + f0 + f2], sn = sinT[pos * 32 + f0 + f2];
                        const float e = v[2*f2], o = v[2*f2 + 1];
                        v[2*f2]     = e * c - o * sn;
                        v[2*f2 + 1] = o * c + e * sn;
                    }
                }
                if (MODE == MODE_Q) {
                    #pragma unroll
                    for (int j = 0; j < 32; j++) v[j] *= QSCALE;
                }
                uint32_t hp[16], lp[16];
                #pragma unroll
                for (int j2 = 0; j2 < 16; j2++) {
                    const float v0 = v[2*j2], v1 = v[2*j2 + 1];
                    const uint16_t h0 = bf16bits(v0), h1 = bf16bits(v1);
                    const uint16_t l0 = bf16bits(v0 - bf16val(h0));
                    const uint16_t l1 = bf16bits(v1 - bf16val(h1));
                    hp[j2] = (uint32_t)h0 | ((uint32_t)h1 << 16);
                    lp[j2] = (uint32_t)l0 | ((uint32_t)l1 << 16);
                }
                const size_t base = ((size_t)(b * H_ + h) * S_ + s) * HD_ + d0;
                uint32_t* dh_ = (uint32_t*)(((MODE == MODE_Q) ? g_Qhib : g_Khib) + base);
                uint32_t* dl_ = (uint32_t*)(((MODE == MODE_Q) ? g_Qlob : g_Klob) + base);
                #pragma unroll
                for (int j4 = 0; j4 < 4; j4++) {
                    *(uint4*)(dh_ + j4 * 4) = make_uint4(hp[j4*4], hp[j4*4+1], hp[j4*4+2], hp[j4*4+3]);
                    *(uint4*)(dl_ + j4 * 4) = make_uint4(lp[j4*4], lp[j4*4+1], lp[j4*4+2], lp[j4*4+3]);
                }
            }
        }
    }
    TCGEN05_FENCE_BEFORE();
    __syncthreads();
    if (tid == 0) { MBARRIER_INVAL(sb + SM_BAR0); MBARRIER_INVAL(sb + SM_BAR1); }
    if (wid == 0) TCGEN05_DEALLOC(tmem_base, 512);
#else
    // ---------------- SIMT fp32 fallback (2 m-blocks x 2 n-halves) --------
    const float* Af = (const float*)Ain;
    const float* Wf = (const float*)Wt;
    float* As = (float*)smem;
    float* Ws = As + 16 * 132;
    const int tx = tid & 15, ty = tid >> 4;
    const int lr = tid >> 1;
    const int lk = (tid & 1) * 8;

    for (int mb = 0; mb < 2; mb++) {
        const int m0 = blockIdx.y * 256 + mb * 128;
        for (int nb = 0; nb < 2; nb++) {
            const int n0 = blockIdx.x * GT_N + nb * 128;

            float acc[2][2][4][4];
            #pragma unroll
            for (int p = 0; p < 2; p++)
                #pragma unroll
                for (int q = 0; q < 2; q++)
                    #pragma unroll
                    for (int i = 0; i < 4; i++)
                        #pragma unroll
                        for (int j = 0; j < 4; j++) acc[p][q][i][j] = 0.f;

            const float* Ap = Af + (size_t)(m0 + lr) * KD_ + lk;
            const float* Wp = Wf + (size_t)(n0 + lr) * KD_ + lk;

            for (int kc = 0; kc < KD_; kc += 16) {
                float4 a0 = *(const float4*)(Ap + kc);
                float4 a1 = *(const float4*)(Ap + kc + 4);
                float4 w0 = *(const float4*)(Wp + kc);
                float4 w1 = *(const float4*)(Wp + kc + 4);
                __syncthreads();
                As[(lk + 0) * 132 + lr] = a0.x; As[(lk + 1) * 132 + lr] = a0.y;
                As[(lk + 2) * 132 + lr] = a0.z; As[(lk + 3) * 132 + lr] = a0.w;
                As[(lk + 4) * 132 + lr] = a1.x; As[(lk + 5) * 132 + lr] = a1.y;
                As[(lk + 6) * 132 + lr] = a1.z; As[(lk + 7) * 132 + lr] = a1.w;
                Ws[(lk + 0) * 132 + lr] = w0.x; Ws[(lk + 1) * 132 + lr] = w0.y;
                Ws[(lk + 2) * 132 + lr] = w0.z; Ws[(lk + 3) * 132 + lr] = w0.w;
                Ws[(lk + 4) * 132 + lr] = w1.x; Ws[(lk + 5) * 132 + lr] = w1.y;
                Ws[(lk + 6) * 132 + lr] = w1.z; Ws[(lk + 7) * 132 + lr] = w1.w;
                __syncthreads();
                #pragma unroll
                for (int kk = 0; kk < 16; kk++) {
                    float4 av0 = *(const float4*)&As[kk * 132 + ty * 4];
                    float4 av1 = *(const float4*)&As[kk * 132 + 64 + ty * 4];
                    float4 bv0 = *(const float4*)&Ws[kk * 132 + tx * 4];
                    float4 bv1 = *(const float4*)&Ws[kk * 132 + 64 + tx * 4];
                    float af[2][4] = {{av0.x, av0.y, av0.z, av0.w}, {av1.x, av1.y, av1.z, av1.w}};
                    float bf[2][4] = {{bv0.x, bv0.y, bv0.z, bv0.w}, {bv1.x, bv1.y, bv1.z, bv1.w}};
                    #pragma unroll
                    for (int p = 0; p < 2; p++)
                        #pragma unroll
                        for (int q = 0; q < 2; q++)
                            #pragma unroll
                            for (int i = 0; i < 4; i++)
                                #pragma unroll
                                for (int j = 0; j < 4; j++)
                                    acc[p][q][i][j] += af[p][i] * bf[q][j];
                }
            }

            if (MODE == MODE_PLAIN) {
                #pragma unroll
                for (int p = 0; p < 2; p++)
                    #pragma unroll
                    for (int i = 0; i < 4; i++) {
                        const int m = m0 + p * 64 + ty * 4 + i;
                        #pragma unroll
                        for (int q = 0; q < 2; q++) {
                            const int n = n0 + q * 64 + tx * 4;
                            float4 v = make_float4(acc[p][q][i][0], acc[p][q][i][1],
                                                   acc[p][q][i][2], acc[p][q][i][3]);
                            *(float4*)&Cout[(size_t)m * DM_ + n] = v;
                        }
                    }
            } else {
                const int ur = use_rope[0];
                #pragma unroll
                for (int p = 0; p < 2; p++)
                    #pragma unroll
                    for (int i = 0; i < 4; i++) {
                        const int m = m0 + p * 64 + ty * 4 + i;
                        const int b = m / S_, s = m % S_;
                        const int pos = (MODE == MODE_V) ? 0 : tokpos[s];
                        #pragma unroll
                        for (int q = 0; q < 2; q++) {
                            const int cn = n0 + q * 64 + tx * 4;
                            const int h  = cn >> 6;
                            const int d0 = cn & 63;
                            float v0 = acc[p][q][i][0], v1 = acc[p][q][i][1];
                            float v2 = acc[p][q][i][2], v3 = acc[p][q][i][3];
                            if (MODE != MODE_V && ur) {
                                const int f = d0 >> 1;
                                float c0 = cosT[pos * 32 + f],     s0 = sinT[pos * 32 + f];
                                float c1 = cosT[pos * 32 + f + 1], s1 = sinT[pos * 32 + f + 1];
                                float e0 = v0, o0 = v1, e1 = v2, o1 = v3;
                                v0 = e0 * c0 - o0 * s0;  v1 = o0 * c0 + e0 * s0;
                                v2 = e1 * c1 - o1 * s1;  v3 = o1 * c1 + e1 * s1;
                            }
                            if (MODE == MODE_Q) { v0 *= QSCALE; v1 *= QSCALE; v2 *= QSCALE; v3 *= QSCALE; }
                            if (MODE == MODE_V) {
                                uint32_t* o = g_Vt + ((size_t)(b * H_ + h) * HD_ + d0) * S_ + s;
                                o[0] = f2tf32(v0); o[(size_t)S_] = f2tf32(v1);
                                o[(size_t)2*S_] = f2tf32(v2); o[(size_t)3*S_] = f2tf32(v3);
                            } else {
                                const size_t base = ((size_t)(b * H_ + h) * S_ + s) * HD_ + d0;
                                uint16_t* oh = ((MODE == MODE_Q) ? g_Qhib : g_Khib) + base;
                                uint16_t* ol = ((MODE == MODE_Q) ? g_Qlob : g_Klob) + base;
                                float vv[4] = {v0, v1, v2, v3};
                                #pragma unroll
                                for (int t = 0; t < 4; t++) {
                                    uint16_t hb = bf16bits(vv[t]);
                                    oh[t] = hb;
                                    ol[t] = bf16bits(vv[t] - bf16val(hb));
                                }
                            }
                        }
                    }
            }
            __syncthreads();
        }
    }
#endif
}

// ---------------------------------------------------------------------------
// tcgen05 causal flash attention. BM=128, BN=64. QK = bf16 hi/lo 3-term MMA;
// P*V = tf32 TS-mode. Occupancy 2 (smem 84KB, TMEM 256 cols).
// Producer/consumer named barriers: comp threads never block at tile syncs.
// TMEM: S0 @0 (64), S1 @64 (64), O @128 (64), P @192 (64).
// ---------------------------------------------------------------------------
#define AT_BM 128
#define AT_BN 64
#define AS_TMEMP 0
#define AS_BAR1  16
#define AS_BAR2  24
#define AS_PSUM  32                      // 256 floats
#define AS_QHI   2048                    // 16KB: 128 rows x 128B (64 bf16)
#define AS_QLO   (AS_QHI + 16384)        // 16KB
#define AS_KHI   (AS_QLO + 16384)        // 8KB: 64 rows x 128B
#define AS_KLO   (AS_KHI + 8192)         // 8KB
#define AS_VT0   (AS_KLO + 8192)         // 16KB: 2 chunks x (64 d x 32 kv x 4B)
#define AS_VT1   (AS_VT0 + 16384)        // 16KB
#define AT_SMEM  (AS_VT1 + 16384)        // 83968 bytes -> 2 CTAs/SM

#define TM_S0 0
#define TM_S1 64
#define TM_O  128
#define TM_P  192

#if HAS_TCGEN05
// MMA1: S[128,64] = Qhi*Khi + Qhi*Klo + Qlo*Khi (bf16, K=64 -> 4 K16-steps each)
__device__ __forceinline__ void issue_mma1(uint32_t sb, uint32_t tb, uint32_t tmDst) {
    const uint32_t aoffs[3] = {AS_QHI, AS_QHI, AS_QLO};
    const uint32_t boffs[3] = {AS_KHI, AS_KLO, AS_KHI};
    int disp = 0;
    #pragma unroll
    for (int pr = 0; pr < 3; pr++) {
        const uint64_t ad = MAKE_SMEM_DESC(sb + aoffs[pr]);
        const uint64_t bd = MAKE_SMEM_DESC(sb + boffs[pr]);
        #pragma unroll
        for (int s = 0; s < 4; s++) {
            mma_bf16_ss(tb + tmDst, ad + s * 2, bd + s * 2, IDESC_BF16_N64, disp ? 1u : 0u);
            disp++;
        }
    }
    TCGEN05_COMMIT(sb + AS_BAR1);
}
// Stage one K tile (hi+lo, 64 rows x 128B each): r = tid>>2, 2 units each buffer.
__device__ __forceinline__ void stage_k(uint32_t sb, int bh, int kt, int tid) {
    const int r = tid >> 2, part = tid & 3;
    const size_t goff = ((size_t)bh * S_ + (size_t)kt * AT_BN + r) * HD_;
    #pragma unroll
    for (int i = 0; i < 2; i++) {
        const int u = part * 2 + i;
        const uint32_t so = SMEM_SWIZZLE_128B((uint32_t)(r * 128 + u * 16));
        CP_ASYNC16(sb + AS_KHI + so, g_Khib + goff + u * 8);
        CP_ASYNC16(sb + AS_KLO + so, g_Klob + goff + u * 8);
    }
}
// Stage one V tile (tf32, 2 chunks x [64 d x 32 kv]): d = tid>>2, 4 units each.
__device__ __forceinline__ void stage_v(uint32_t sb, int bh, int kt, int tid, uint32_t vOff) {
    const int d = tid >> 2, rem = tid & 3;
    const uint32_t* vrow = g_Vt + ((size_t)bh * HD_ + d) * S_ + (size_t)kt * AT_BN;
    #pragma unroll
    for (int i = 0; i < 4; i++) {
        const int u = rem * 4 + i;          // 0..15 over 2 chunks x 8 units
        const int chunk = u >> 3, w = u & 7;
        const uint32_t so = SMEM_SWIZZLE_128B((uint32_t)(d * 128 + w * 16));
        CP_ASYNC16(sb + vOff + chunk * 8192 + so, vrow + chunk * 32 + w * 4);
    }
}
#endif

__global__ __launch_bounds__(288, 2)
void attn_tc()
{
    const int tid = threadIdx.x;
    const int qt = (int)(gridDim.x - 1 - blockIdx.x);   // big tiles launch first
    const int h = blockIdx.y, b = blockIdx.z;
    const int bh = b * H_ + h;

#if HAS_TCGEN05
    extern __shared__ char smem[];
    const uint32_t sb = smem_to_u32(smem);
    const int wid = tid >> 5, lid = tid & 31;
    const int wg = (tid >> 7) & 1;                      // column half (32 of 64)
    const bool comp = (tid < 256);
    const bool mmaw = (wid == 8);

    if (wid == 0) { TCGEN05_ALLOC(sb + AS_TMEMP, 256); TCGEN05_RELINQUISH(); }
    if (tid == 0) { MBARRIER_INIT(sb + AS_BAR1, 1); MBARRIER_INIT(sb + AS_BAR2, 1); }
    __syncthreads();
    uint32_t tb;
    asm volatile("ld.shared.b32 %0, [%1];" : "=r"(tb) : "r"(sb + AS_TMEMP));

    // ---- Prologue staging: Q(hi/lo), K(0), V(0) — all cp.async ----
    if (comp) {
        const int r = tid >> 1, part = tid & 1;
        const size_t qoff = ((size_t)bh * S_ + (size_t)qt * AT_BM + r) * HD_;
        #pragma unroll
        for (int i = 0; i < 4; i++) {
            const int u = part * 4 + i;
            const uint32_t so = SMEM_SWIZZLE_128B((uint32_t)(r * 128 + u * 16));
            CP_ASYNC16(sb + AS_QHI + so, g_Qhib + qoff + u * 8);
            CP_ASYNC16(sb + AS_QLO + so, g_Qlob + qoff + u * 8);
        }
        stage_k(sb, bh, 0, tid);
        stage_v(sb, bh, 0, tid, AS_VT0);
        CP_COMMIT();
        CP_WAIT0();
        FENCE_PROXY_ASYNC_SHARED_CTA();
    }
    __syncthreads();

    if (mmaw && elect_one_pred()) issue_mma1(sb, tb, TM_S0);

    float l = 0.f;
    int ph1 = 0, ph2 = 0;
    const int row   = (wid & 3) * 32 + lid;
    const int qglob = qt * AT_BM + row;
    const int nt = 2 * qt + 2;                          // kv tiles of 64

    for (int kt = 0; kt < nt; kt++) {
        const uint32_t sCur = (kt & 1) ? TM_S1 : TM_S0;
        const uint32_t sNxt = (kt & 1) ? TM_S0 : TM_S1;
        const uint32_t vCur = (kt & 1) ? AS_VT1 : AS_VT0;
        const uint32_t vNxt = (kt & 1) ? AS_VT0 : AS_VT1;
        const bool more = (kt < nt - 1);

        uint32_t sreg[32];

        if (comp) {
            // 1. MMA1(kt) done (K smem free to overwrite)
            MBARRIER_WAIT_PARITY(sb + AS_BAR1, ph1); ph1 ^= 1;
            TCGEN05_FENCE_AFTER();

            // 2. Kick off K(kt+1) cp.asyncs (run under LDTM)
            if (more) { stage_k(sb, bh, kt + 1, tid); CP_COMMIT(); }

            // 3. LDTM S(kt): warp rows, this wg's 32 cols
            TCGEN05_LD_32X32B_X32(sreg, tb + sCur + wg * 32);
            TCGEN05_WAIT_LD();
            TCGEN05_FENCE_BEFORE();

            // 4. K staged -> fence -> non-blocking arrive (bar 1)
            if (more) {
                CP_WAIT0(); FENCE_PROXY_ASYNC_SHARED_CTA();
                NAMED_BAR_ARRIVE(1, 288);
            }
        }
        if (more && mmaw) {
            NAMED_BAR_SYNC(1, 288);
            TCGEN05_FENCE_AFTER();
            if (elect_one_pred()) issue_mma1(sb, tb, sNxt);     // overlaps softmax
        }

        if (comp) {
            // 5. MMA2(kt-1) done (frees P TMEM + vNxt smem)
            if (kt > 0) { MBARRIER_WAIT_PARITY(sb + AS_BAR2, ph2); ph2 ^= 1; }

            // 6. Kick off V(kt+1) cp.asyncs (run under softmax)
            if (more) { stage_v(sb, bh, kt + 1, tid, vNxt); CP_COMMIT(); }

            // 7. Softmax (no max, exp2 — log2e folded into Q)
            const int kvbase = kt * AT_BN + wg * 32;
            #pragma unroll
            for (int j = 0; j < 32; j++) {
                const float p = (kvbase + j <= qglob) ? exp2f(__uint_as_float(sreg[j])) : 0.f;
                l += p;
                sreg[j] = f2tf32(p);
            }

            // 8. STTM P
            TCGEN05_ST_32X32B_X32(tb + TM_P + wg * 32, sreg);
            TCGEN05_WAIT_ST();
            TCGEN05_FENCE_BEFORE();

            // 9. V staged -> fence -> non-blocking arrive (bar 2)
            if (more) { CP_WAIT0(); FENCE_PROXY_ASYNC_SHARED_CTA(); }
            NAMED_BAR_ARRIVE(2, 288);
        }
        // 10. MMA2(kt): O += P(TMEM)[128x64kv] * V^T(kt), TS mode tf32
        if (mmaw) {
            NAMED_BAR_SYNC(2, 288);
            TCGEN05_FENCE_AFTER();
            if (elect_one_pred()) {
                #pragma unroll
                for (int c = 0; c < 2; c++) {
                    const uint64_t bd = MAKE_SMEM_DESC(sb + vCur + c * 8192);
                    #pragma unroll
                    for (int s = 0; s < 4; s++) {
                        mma_tf32_ts(tb + TM_O, tb + TM_P + c * 32 + s * 8, bd + s * 2,
                                    IDESC_TF32_N64, (kt > 0 || c > 0 || s > 0) ? 1u : 0u);
                    }
                }
                TCGEN05_COMMIT(sb + AS_BAR2);
            }
        }
    }

    // ---- Final MMA2 drain + epilogue (writes pre-packed tf32 g_Yt) ----
    if (comp) {
        MBARRIER_WAIT_PARITY(sb + AS_BAR2, ph2);
        TCGEN05_FENCE_AFTER();
        ((float*)(smem + AS_PSUM))[tid] = l;
    }
    __syncthreads();

    if (comp) {
        const float ltot = l + ((float*)(smem + AS_PSUM))[tid ^ 128];
        uint32_t od[32];
        TCGEN05_LD_32X32B_X32(od, tb + TM_O + wg * 32);
        TCGEN05_WAIT_LD();
        TCGEN05_FENCE_BEFORE();

        const float inv = 1.f / ltot;
        uint32_t* dst = g_Yt + ((size_t)(b * S_ + qt * AT_BM + row)) * DM_ + h * 64 + wg * 32;
        #pragma unroll
        for (int j4 = 0; j4 < 8; j4++) {
            *(uint4*)(dst + j4 * 4) = make_uint4(
                f2tf32(__uint_as_float(od[j4*4+0]) * inv), f2tf32(__uint_as_float(od[j4*4+1]) * inv),
                f2tf32(__uint_as_float(od[j4*4+2]) * inv), f2tf32(__uint_as_float(od[j4*4+3]) * inv));
        }
    }
    __syncthreads();
    if (tid == 0) { MBARRIER_INVAL(sb + AS_BAR1); MBARRIER_INVAL(sb + AS_BAR2); }
    if (wid == 0) TCGEN05_DEALLOC(tb, 256);
#else
    // ---- SIMT fallback (portable pass only; never selected on GB300) ----
    if (tid < 256) {
        const int r = tid >> 1, dh = tid & 1;
        const int qg = qt * AT_BM + r;
        const size_t qoff = ((size_t)bh * S_ + qg) * HD_;
        float qv[64];
        #pragma unroll
        for (int d = 0; d < 64; d++)
            qv[d] = bf16val(g_Qhib[qoff + d]) + bf16val(g_Qlob[qoff + d]);
        float acc[32];
        #pragma unroll
        for (int d = 0; d < 32; d++) acc[d] = 0.f;
        float l = 0.f;
        for (int kv = 0; kv <= qg; kv++) {
            const size_t koff = ((size_t)bh * S_ + kv) * HD_;
            float s = 0.f;
            for (int d = 0; d < 64; d++)
                s += qv[d] * (bf16val(g_Khib[koff + d]) + bf16val(g_Klob[koff + d]));
            const float p = exp2f(s);
            l += p;
            for (int d = 0; d < 32; d++)
                acc[d] += p * __uint_as_float(g_Vt[((size_t)bh * HD_ + dh * 32 + d) * S_ + kv]);
        }
        const float inv = 1.f / l;
        uint32_t* dst = g_Yt + ((size_t)(b * S_ + qg)) * DM_ + h * 64 + dh * 32;
        for (int d = 0; d < 32; d++) dst[d] = f2tf32(acc[d] * inv);
    }
#endif
}

extern "C" void kernel_launch(void* const* d_in, const int* in_sizes, int n_in,
                              void* d_out, int out_size)
{
    const float* x       = (const float*)d_in[0];
    const int*   tokpos  = (const int*)  d_in[1];
    const int*   userope = (const int*)  d_in[2];
    const float* Wq      = (const float*)d_in[3];
    const float* Wk      = (const float*)d_in[4];
    const float* Wv      = (const float*)d_in[5];
    const float* Wo      = (const float*)d_in[6];
    const float* cosT    = (const float*)d_in[7];
    const float* sinT    = (const float*)d_in[8];
    float* out = (float*)d_out;

    cudaFuncSetAttribute(gemm_tc<MODE_Q>,     cudaFuncAttributeMaxDynamicSharedMemorySize, GT_SMEM_SZ);
    cudaFuncSetAttribute(gemm_tc<MODE_K>,     cudaFuncAttributeMaxDynamicSharedMemorySize, GT_SMEM_SZ);
    cudaFuncSetAttribute(gemm_tc<MODE_V>,     cudaFuncAttributeMaxDynamicSharedMemorySize, GT_SMEM_SZ);
    cudaFuncSetAttribute(gemm_tc<MODE_PLAIN>, cudaFuncAttributeMaxDynamicSharedMemorySize, GT_SMEM_SZ);
    cudaFuncSetAttribute(attn_tc,             cudaFuncAttributeMaxDynamicSharedMemorySize, AT_SMEM);

    uint32_t *dXt, *dWqt, *dWkt, *dWvt, *dWot;
    cudaGetSymbolAddress((void**)&dXt,  g_Xt);
    cudaGetSymbolAddress((void**)&dWqt, g_Wqt);
    cudaGetSymbolAddress((void**)&dWkt, g_Wkt);
    cudaGetSymbolAddress((void**)&dWvt, g_Wvt);
    cudaGetSymbolAddress((void**)&dWot, g_Wot);

    // Pre-pack operands to tf32 bits (bit-identical to former per-CTA staging cvt)
    pack_tf32<<<(B_*S_*DM_) / 1024, 256>>>(x,  dXt);
    pack_tf32<<<(DM_*DM_)   / 1024, 256>>>(Wq, dWqt);
    pack_tf32<<<(DM_*DM_)   / 1024, 256>>>(Wk, dWkt);
    pack_tf32<<<(DM_*DM_)   / 1024, 256>>>(Wv, dWvt);
    pack_tf32<<<(DM_*DM_)   / 1024, 256>>>(Wo, dWot);

    dim3 gg(DM_ / GT_N, (B_ * S_) / 256);  // (4, 16)

    gemm_tc<MODE_Q><<<gg, 256, GT_SMEM_SZ>>>(dXt, nullptr, dWqt, userope, tokpos, cosT, sinT);
    gemm_tc<MODE_K><<<gg, 256, GT_SMEM_SZ>>>(dXt, nullptr, dWkt, userope, tokpos, cosT, sinT);
    gemm_tc<MODE_V><<<gg, 256, GT_SMEM_SZ>>>(dXt, nullptr, dWvt, userope, tokpos, cosT, sinT);

    attn_tc<<<dim3(S_ / AT_BM, H_, B_), 288, AT_SMEM>>>();

    gemm_tc<MODE_PLAIN><<<gg, 256, GT_SMEM_SZ>>>(nullptr, out, dWot, userope, tokpos, cosT, sinT);
}